// round 15
// baseline (speedup 1.0000x reference)
#include <cuda_runtime.h>
#include <cuda_fp16.h>
#include <cstdint>

// Problem constants
#define BB 8
#define SS 2048
#define DD 512
#define PP 64
#define MTOT (BB * SS)   // 16384

// ---------------------------------------------------------------------------
// Scratch (__device__ globals)
// ---------------------------------------------------------------------------
__device__ __align__(16) __half g_Wo[512 * 64];      // Wo^T [n=512][k=64] fp16
__device__ __align__(16) __half g_x[(size_t)3 * MTOT * 64];  // q|k|v [region][m][p]

// ---------------------------------------------------------------------------
// Helpers
// ---------------------------------------------------------------------------
__device__ __forceinline__ uint32_t smem_u32(const void* p) {
    uint32_t a;
    asm("{ .reg .u64 t; cvta.to.shared.u64 t, %1; cvt.u32.u64 %0, t; }"
        : "=r"(a) : "l"(p));
    return a;
}
__device__ __forceinline__ uint32_t packh2(float lo, float hi) {
    __half2 h = __floats2half2_rn(lo, hi);
    return *(uint32_t*)&h;
}
__device__ __forceinline__ float ex2(float x) {
    float y;
    asm("ex2.approx.f32 %0, %1;" : "=f"(y) : "f"(x));
    return y;
}
// m16n8k16 fp16 mma, fp32 accumulate
__device__ __forceinline__ void mma16816(float c[4], const uint32_t a[4],
                                         const uint32_t b[2]) {
    asm volatile(
        "mma.sync.aligned.m16n8k16.row.col.f32.f16.f16.f32 "
        "{%0,%1,%2,%3}, {%4,%5,%6,%7}, {%8,%9}, {%0,%1,%2,%3};\n"
        : "+f"(c[0]), "+f"(c[1]), "+f"(c[2]), "+f"(c[3])
        : "r"(a[0]), "r"(a[1]), "r"(a[2]), "r"(a[3]), "r"(b[0]), "r"(b[1]));
}
__device__ __forceinline__ void ldsm4(uint32_t r[4], uint32_t addr) {
    asm volatile("ldmatrix.sync.aligned.m8n8.x4.shared.b16 {%0,%1,%2,%3}, [%4];"
                 : "=r"(r[0]), "=r"(r[1]), "=r"(r[2]), "=r"(r[3]) : "r"(addr));
}
__device__ __forceinline__ void ldsm4t(uint32_t r[4], uint32_t addr) {
    asm volatile("ldmatrix.sync.aligned.m8n8.x4.trans.shared.b16 {%0,%1,%2,%3}, [%4];"
                 : "=r"(r[0]), "=r"(r[1]), "=r"(r[2]), "=r"(r[3]) : "r"(addr));
}
#define CPA(dst, src) \
    asm volatile("cp.async.cg.shared.global [%0], [%1], 16;" \
                 :: "r"(dst), "l"(src) : "memory")
#define CPC() asm volatile("cp.async.commit_group;" ::: "memory")
#define CPW(n) asm volatile("cp.async.wait_group %0;" :: "n"(n) : "memory")

#define STR 72          // fp16 row stride in elements (144 B)
#define ROWB 144
#define QSC (0.125f * 1.4426950408889634f)   // 1/sqrt(P) * log2(e)

// ---------------------------------------------------------------------------
// Merged QKV GEMM (unchanged from round 14): one CTA computes all three
// regions for a 128-row m-tile. 384 threads = 12 warps: wm=w&3, wn=w>>2.
// ---------------------------------------------------------------------------
__global__ __launch_bounds__(384) void gemm_qkv(
    const float* __restrict__ Af,
    const float* __restrict__ Wq, const float* __restrict__ Wk,
    const float* __restrict__ Wv,
    const float* __restrict__ bq, const float* __restrict__ bk,
    const float* __restrict__ bv,
    const float* __restrict__ Wo, __half* __restrict__ Chg) {
    extern __shared__ char smc[];
    __half* As = (__half*)smc;
    __half* Bs = As + 128 * STR;
    const uint32_t smb = smem_u32(smc);
    const uint32_t Ao = smb, Bo = smb + 128 * ROWB;

    int tid = threadIdx.x, w = tid >> 5, l = tid & 31;
    int wm = w & 3, wn = w >> 2;
    int m0 = blockIdx.x * 128;

    // --- Wo^T pack prologue: 8 CTAs, one 64x64 tile each (register transpose)
    if (blockIdx.x < 8 && tid < 256) {
        int dt = blockIdx.x;
        int rp = tid >> 3, f8 = tid & 7;
        #pragma unroll
        for (int i = 0; i < 2; i++) {
            int f4 = f8 + i * 8;
            float4 a0 = *(const float4*)(Wo + (size_t)(rp * 2)     * 512 + dt * 64 + f4 * 4);
            float4 a1 = *(const float4*)(Wo + (size_t)(rp * 2 + 1) * 512 + dt * 64 + f4 * 4);
            *(uint32_t*)&g_Wo[(size_t)(dt * 64 + f4 * 4 + 0) * 64 + rp * 2] = packh2(a0.x, a1.x);
            *(uint32_t*)&g_Wo[(size_t)(dt * 64 + f4 * 4 + 1) * 64 + rp * 2] = packh2(a0.y, a1.y);
            *(uint32_t*)&g_Wo[(size_t)(dt * 64 + f4 * 4 + 2) * 64 + rp * 2] = packh2(a0.z, a1.z);
            *(uint32_t*)&g_Wo[(size_t)(dt * 64 + f4 * 4 + 3) * 64 + rp * 2] = packh2(a0.w, a1.w);
        }
    }

    float4 aP[6];
    float4 bP0[4], bP1[4];
    #pragma unroll
    for (int i = 0; i < 6; i++) {
        int idx = tid + i * 384;
        if (idx < 2048) {
            int rr = idx >> 4, c4 = idx & 15;
            aP[i] = *(const float4*)(Af + (size_t)(m0 + rr) * DD + c4 * 4);
        }
    }
    #pragma unroll
    for (int i = 0; i < 4; i++) {
        int tix = tid + i * 384;
        int rg2 = tix >> 9, t5 = tix & 511, kp = t5 >> 4, n4 = t5 & 15;
        const float* Wsrc = (rg2 == 0) ? Wq : ((rg2 == 1) ? Wk : Wv);
        const float* base = Wsrc + (size_t)(kp * 2) * 64 + n4 * 4;
        bP0[i] = *(const float4*)base;
        bP1[i] = *(const float4*)(base + 64);
    }

    float c[2][8][4] = {};

    for (int k0 = 0; k0 < DD; k0 += 64) {
        #pragma unroll
        for (int i = 0; i < 6; i++) {
            int idx = tid + i * 384;
            if (idx < 2048) {
                int rr = idx >> 4, c4 = idx & 15;
                float4 v = aP[i];
                *(uint2*)&As[rr * STR + c4 * 4] =
                    make_uint2(packh2(v.x, v.y), packh2(v.z, v.w));
            }
        }
        #pragma unroll
        for (int i = 0; i < 4; i++) {
            int tix = tid + i * 384;
            int rg2 = tix >> 9, t5 = tix & 511, kp = t5 >> 4, n4 = t5 & 15;
            float s = (rg2 == 0) ? QSC : 1.f;
            float4 v0 = bP0[i], v1 = bP1[i];
            int rn = rg2 * 64 + n4 * 4;
            *(uint32_t*)&Bs[(rn + 0) * STR + kp * 2] = packh2(v0.x * s, v1.x * s);
            *(uint32_t*)&Bs[(rn + 1) * STR + kp * 2] = packh2(v0.y * s, v1.y * s);
            *(uint32_t*)&Bs[(rn + 2) * STR + kp * 2] = packh2(v0.z * s, v1.z * s);
            *(uint32_t*)&Bs[(rn + 3) * STR + kp * 2] = packh2(v0.w * s, v1.w * s);
        }
        __syncthreads();

        if (k0 + 64 < DD) {
            int kn = k0 + 64;
            #pragma unroll
            for (int i = 0; i < 6; i++) {
                int idx = tid + i * 384;
                if (idx < 2048) {
                    int rr = idx >> 4, c4 = idx & 15;
                    aP[i] = *(const float4*)(Af + (size_t)(m0 + rr) * DD + kn + c4 * 4);
                }
            }
            #pragma unroll
            for (int i = 0; i < 4; i++) {
                int tix = tid + i * 384;
                int rg2 = tix >> 9, t5 = tix & 511, kp = t5 >> 4, n4 = t5 & 15;
                const float* Wsrc = (rg2 == 0) ? Wq : ((rg2 == 1) ? Wk : Wv);
                const float* base = Wsrc + (size_t)(kn + kp * 2) * 64 + n4 * 4;
                bP0[i] = *(const float4*)base;
                bP1[i] = *(const float4*)(base + 64);
            }
        }

        {
            int r = l & 15, cc = l >> 4;
            #pragma unroll
            for (int j = 0; j < 4; j++) {
                uint32_t a0[4], a1[4];
                uint32_t aoff = (wm * 32 + r) * ROWB + (j * 2 + cc) * 16;
                ldsm4(a0, Ao + aoff);
                ldsm4(a1, Ao + aoff + 16 * ROWB);
                #pragma unroll
                for (int np = 0; np < 4; np++) {
                    uint32_t bb[4];
                    ldsm4(bb, Bo + (wn * 64 + np * 16 + r) * ROWB + (j * 2 + cc) * 16);
                    uint32_t be[2] = { bb[0], bb[2] }, bo_[2] = { bb[1], bb[3] };
                    mma16816(c[0][np * 2],     a0, be);
                    mma16816(c[1][np * 2],     a1, be);
                    mma16816(c[0][np * 2 + 1], a0, bo_);
                    mma16816(c[1][np * 2 + 1], a1, bo_);
                }
            }
        }
        __syncthreads();
    }

    size_t reg = (size_t)wn * MTOT * 64;
    const float* bsrc = (wn == 0) ? bq : ((wn == 1) ? bk : bv);
    const float bscale = (wn == 0) ? QSC : 1.f;
    #pragma unroll
    for (int mt = 0; mt < 2; mt++)
        #pragma unroll
        for (int nt = 0; nt < 8; nt++) {
            int row = m0 + wm * 32 + mt * 16 + (l >> 2);
            int col = nt * 8 + (l & 3) * 2;
            float b0 = bsrc[col] * bscale, b1 = bsrc[col + 1] * bscale;
            *(uint32_t*)&Chg[reg + (size_t)row * 64 + col] =
                packh2(c[mt][nt][0] + b0, c[mt][nt][1] + b1);
            *(uint32_t*)&Chg[reg + (size_t)(row + 8) * 64 + col] =
                packh2(c[mt][nt][2] + b0, c[mt][nt][3] + b1);
        }
}

// ---------------------------------------------------------------------------
// Fused flash attention + output projection.
// 4-stage KV ring, ONE barrier per tile, FA2 cross-tile pipeline with the
// S(t+1) and PV(t) MMA streams MANUALLY INTERLEAVED (asm volatile fixes
// issue order, so the interleave must be in source). Barrier-free 4-pass Wo
// epilogue (all Wo resident before the pass loop).
// No-max softmax (bounded scores, shift-invariance). Mask term: no-op.
// ---------------------------------------------------------------------------
#define TILEB (64 * ROWB)      // 9216 B per 64x64 fp16 tile
#define STAGEB (2 * TILEB)     // k, v (also one 128-row Wo pass)
#define NT (SS / 64)           // 32; NT&3 == 0
#define TSTEP (64 * 128)       // global bytes per KV tile
#define OT_OFF  (4 * STAGEB)
#define LP_OFF  (4 * STAGEB + TILEB)
#define SM_ATTN (4 * STAGEB + TILEB + 8 * 16 * 4)
#define P32STR 66              // fp32 partial-O row stride (floats)

__device__ __forceinline__ void load_stage(uint32_t stb, const char* k,
                                           const char* v, int tid) {
    #pragma unroll
    for (int i = 0; i < 2; i++) {
        int idx = tid + i * 256;
        int row = idx >> 3, c = idx & 7;
        uint32_t d = stb + row * ROWB + c * 16;
        size_t g = (size_t)row * 128 + c * 16;
        CPA(d,         k + g);
        CPA(d + TILEB, v + g);
    }
}
__device__ __forceinline__ void load_wo(uint32_t stb, int pass, int tid) {
    const char* wop = (const char*)g_Wo;
    #pragma unroll
    for (int i = 0; i < 4; i++) {
        int idx = tid + i * 256;
        int row = idx >> 3, c = idx & 7;
        CPA(stb + row * ROWB + c * 16,
            wop + ((size_t)(pass * 128 + row) * 64 + c * 8) * 2);
    }
}

__device__ __forceinline__ void spass_h(float s[4][4], const uint32_t qf[4][4],
                                        uint32_t Kb, int kh, int r, int cc) {
    #pragma unroll
    for (int j = 0; j < 4; j++) {
        #pragma unroll
        for (int np = 0; np < 2; np++) {
            uint32_t bb[4];
            ldsm4(bb, Kb + ((kh * 2 + np) * 16 + r) * ROWB + (j * 2 + cc) * 16);
            uint32_t be[2] = { bb[0], bb[2] }, bo_[2] = { bb[1], bb[3] };
            mma16816(s[np * 2],     qf[j], be);
            mma16816(s[np * 2 + 1], qf[j], bo_);
        }
    }
}

// body(t): issue load(t+2)/Wo prefetch; ONE barrier; softmax(scur);
// then INTERLEAVED { snxt = S(t+1) } x { O += P_t V(t) } MMA streams.
__device__ __forceinline__ void attn_body(
    int t, float (&scur)[4][4], float (&snxt)[4][4],
    float (&o)[8][4], float& l0r, float& l1r,
    const uint32_t (&qf)[4][4],
    uint32_t st0, const char* k0p, const char* v0p,
    int kh, int r, int cc, int tid) {
    if (t + 2 < NT) {
        size_t g = (size_t)(t + 2) * TSTEP;
        load_stage(st0 + ((t + 2) & 3) * STAGEB, k0p + g, v0p + g, tid);
        CPC();
        CPW(1);
    } else if (t + 2 == NT) {
        load_wo(st0 + 0 * STAGEB, 0, tid);   // Wo pass 0 -> slot 0
        CPC();
        CPW(1);
    } else {                                 // t == NT-1
        load_wo(st0 + 1 * STAGEB, 1, tid);   // Wo pass 1 -> slot 1
        CPC();
    }
    __syncthreads();

    // softmax on scur (tile t): p = 2^s
    #pragma unroll
    for (int nt = 0; nt < 4; nt++) {
        scur[nt][0] = ex2(scur[nt][0]);
        scur[nt][1] = ex2(scur[nt][1]);
        scur[nt][2] = ex2(scur[nt][2]);
        scur[nt][3] = ex2(scur[nt][3]);
        l0r += scur[nt][0] + scur[nt][1];
        l1r += scur[nt][2] + scur[nt][3];
    }
    uint32_t pf[2][4];
    #pragma unroll
    for (int j = 0; j < 2; j++) {
        const float* s0 = scur[2 * j];
        const float* s1 = scur[2 * j + 1];
        pf[j][0] = packh2(s0[0], s0[1]);
        pf[j][1] = packh2(s0[2], s0[3]);
        pf[j][2] = packh2(s1[0], s1[1]);
        pf[j][3] = packh2(s1[2], s1[3]);
    }

    #pragma unroll
    for (int a = 0; a < 4; a++)
        #pragma unroll
        for (int bq2 = 0; bq2 < 4; bq2++) snxt[a][bq2] = 0.f;

    const uint32_t Kn = st0 + ((t + 1) & 3) * STAGEB;
    const uint32_t Vb = st0 + (t & 3) * STAGEB + TILEB;
    const bool has_next = (t + 1 < NT);

    // interleaved MMA streams: snxt rounds j=0..3, pv rounds j=0..1 (wider)
    #pragma unroll
    for (int j = 0; j < 4; j++) {
        if (has_next) {
            #pragma unroll
            for (int np = 0; np < 2; np++) {
                uint32_t bb[4];
                ldsm4(bb, Kn + ((kh * 2 + np) * 16 + r) * ROWB + (j * 2 + cc) * 16);
                uint32_t be[2] = { bb[0], bb[2] }, bo_[2] = { bb[1], bb[3] };
                mma16816(snxt[np * 2],     qf[j], be);
                mma16816(snxt[np * 2 + 1], qf[j], bo_);
            }
        }
        if (j < 2) {
            #pragma unroll
            for (int np = 0; np < 4; np++) {
                uint32_t bb[4];
                ldsm4t(bb, Vb + (kh * 32 + j * 16 + r) * ROWB + np * 32 + cc * 16);
                uint32_t be[2] = { bb[0], bb[1] }, bo_[2] = { bb[2], bb[3] };
                mma16816(o[np * 2],     pf[j], be);
                mma16816(o[np * 2 + 1], pf[j], bo_);
            }
        }
    }
}

__global__ __launch_bounds__(256) void attn_fused(const float* __restrict__ bo_g,
                                                  float* __restrict__ out) {
    extern __shared__ char smc[];
    const uint32_t st0 = smem_u32(smc);

    int tid = threadIdx.x, w = tid >> 5, l = tid & 31;
    int rg = w & 3, kh = w >> 2;
    int b = blockIdx.y, m0 = blockIdx.x * 64;
    size_t rb = (size_t)b * SS + m0;
    int rbase = rg * 16;
    int r = l & 15, cc = l >> 4;

    const __half* q = g_x + rb * 64;
    const char* k0p = (const char*)(g_x + ((size_t)MTOT + (size_t)b * SS) * 64);
    const char* v0p = (const char*)(g_x + ((size_t)2 * MTOT + (size_t)b * SS) * 64);

    load_stage(st0,          k0p,         v0p,         tid); CPC();
    load_stage(st0 + STAGEB, k0p + TSTEP, v0p + TSTEP, tid); CPC();

    uint32_t qf[4][4];
    {
        int fr = rbase + (l >> 2);
        int fc = (l & 3) * 2;
        #pragma unroll
        for (int j = 0; j < 4; j++) {
            size_t base0 = (size_t)fr * 64 + j * 16 + fc;
            size_t base1 = base0 + 8 * 64;
            qf[j][0] = *(const uint32_t*)(q + base0);
            qf[j][1] = *(const uint32_t*)(q + base1);
            qf[j][2] = *(const uint32_t*)(q + base0 + 8);
            qf[j][3] = *(const uint32_t*)(q + base1 + 8);
        }
    }

    CPW(1);
    __syncthreads();

    float sA[4][4] = {}, sB[4][4] = {};
    spass_h(sA, qf, st0, kh, r, cc);      // S(0)

    float o[8][4] = {};
    float l0r = 0.f, l1r = 0.f;

    for (int t = 0; t < NT; t += 2) {
        attn_body(t,     sA, sB, o, l0r, l1r, qf, st0, k0p, v0p, kh, r, cc, tid);
        attn_body(t + 1, sB, sA, o, l0r, l1r, qf, st0, k0p, v0p, kh, r, cc, tid);
    }

    // quad-reduce partial l
    l0r += __shfl_xor_sync(~0u, l0r, 1);
    l0r += __shfl_xor_sync(~0u, l0r, 2);
    l1r += __shfl_xor_sync(~0u, l1r, 1);
    l1r += __shfl_xor_sync(~0u, l1r, 2);

    // barrier 1: all loop-reads done; publish partials (l everywhere, O->slot2)
    float* lp = (float*)(smc + LP_OFF);
    if ((l & 3) == 0) {
        lp[w * 16 + (l >> 2)]     = l0r;
        lp[w * 16 + 8 + (l >> 2)] = l1r;
    }
    float* p32 = (float*)(smc + 2 * STAGEB);
    if (kh == 1) {
        #pragma unroll
        for (int nt = 0; nt < 8; nt++) {
            int col = nt * 8 + (l & 3) * 2;
            int row = rbase + (l >> 2);
            *(float2*)&p32[row * P32STR + col]       = make_float2(o[nt][0], o[nt][1]);
            *(float2*)&p32[(row + 8) * P32STR + col] = make_float2(o[nt][2], o[nt][3]);
        }
    }
    __syncthreads();

    // slot 3 (tile NT-1) readers all finished before the barrier above
    load_wo(st0 + 3 * STAGEB, 2, tid);
    CPC();

    // kh=0 warps: combine partials, normalize, publish fp16 O tile
    if (kh == 0) {
        float l0c = l0r + lp[(w + 4) * 16 + (l >> 2)];
        float l1c = l1r + lp[(w + 4) * 16 + 8 + (l >> 2)];
        float i0 = 1.f / l0c, i1 = 1.f / l1c;
        __half* ot = (__half*)(smc + OT_OFF);
        #pragma unroll
        for (int nt = 0; nt < 8; nt++) {
            int col = nt * 8 + (l & 3) * 2;
            int row = rbase + (l >> 2);
            float2 a = *(const float2*)&p32[row * P32STR + col];
            float2 bq2 = *(const float2*)&p32[(row + 8) * P32STR + col];
            *(uint32_t*)&ot[row * STR + col] =
                packh2((o[nt][0] + a.x) * i0, (o[nt][1] + a.y) * i0);
            *(uint32_t*)&ot[(row + 8) * STR + col] =
                packh2((o[nt][2] + bq2.x) * i1, (o[nt][3] + bq2.y) * i1);
        }
    }
    __syncthreads();

    // slot 2 (p32) consumed -> safe for Wo pass 3
    load_wo(st0 + 2 * STAGEB, 3, tid);
    CPC();

    // O a-frags from the fp16 tile (OT visible after barrier above)
    uint32_t of[4][4];
    {
        uint32_t OTb = st0 + OT_OFF;
        #pragma unroll
        for (int j = 0; j < 4; j++)
            ldsm4(of[j], OTb + (rbase + r) * ROWB + (j * 2 + cc) * 16);
    }

    CPW(0);            // Wo0..Wo3 all resident
    __syncthreads();

    // 4 Wo passes, slots {0,1,3,2}, ZERO barriers inside.
    const int pass_slot[4] = { 0, 1, 3, 2 };
    size_t r0g = rb + rbase + (l >> 2), r1g = r0g + 8;
    #pragma unroll
    for (int pass = 0; pass < 4; pass++) {
        uint32_t Wb = st0 + pass_slot[pass] * STAGEB;
        #pragma unroll
        for (int np = 0; np < 4; np++) {
            int npg = kh * 4 + np;
            float ce[4] = {}, co[4] = {};
            #pragma unroll
            for (int j = 0; j < 4; j++) {
                uint32_t bb[4];
                ldsm4(bb, Wb + (npg * 16 + r) * ROWB + (j * 2 + cc) * 16);
                uint32_t be[2] = { bb[0], bb[2] }, bo_[2] = { bb[1], bb[3] };
                mma16816(ce, of[j], be);
                mma16816(co, of[j], bo_);
            }
            int c0 = pass * 128 + npg * 16 + (l & 3) * 2;
            int c1 = c0 + 8;
            float be0 = bo_g[c0], be1 = bo_g[c0 + 1];
            float bO0 = bo_g[c1], bO1 = bo_g[c1 + 1];
            *(float2*)&out[r0g * DD + c0] = make_float2(ce[0] + be0, ce[1] + be1);
            *(float2*)&out[r1g * DD + c0] = make_float2(ce[2] + be0, ce[3] + be1);
            *(float2*)&out[r0g * DD + c1] = make_float2(co[0] + bO0, co[1] + bO1);
            *(float2*)&out[r1g * DD + c1] = make_float2(co[2] + bO0, co[3] + bO1);
        }
    }
}

// ---------------------------------------------------------------------------
// kernel_launch
// Inputs: query, attention_mask, Wq, bq, Wk, bk, Wv, bv, Wo, bo
// ---------------------------------------------------------------------------
extern "C" void kernel_launch(void* const* d_in, const int* in_sizes, int n_in,
                              void* d_out, int out_size) {
    const float* query = (const float*)d_in[0];
    const float* Wq = (const float*)d_in[2];
    const float* bq = (const float*)d_in[3];
    const float* Wk = (const float*)d_in[4];
    const float* bk = (const float*)d_in[5];
    const float* Wv = (const float*)d_in[6];
    const float* bv = (const float*)d_in[7];
    const float* Wo = (const float*)d_in[8];
    const float* bo = (const float*)d_in[9];
    float* out = (float*)d_out;

    __half* px;
    cudaGetSymbolAddress((void**)&px, g_x);

    constexpr int SM_GEMM = (128 + 192) * ROWB;   // 46080 B

    // 1) merged QKV projection (one A convert shared by all 3 regions)
    cudaFuncSetAttribute(gemm_qkv,
                         cudaFuncAttributeMaxDynamicSharedMemorySize, SM_GEMM);
    gemm_qkv<<<MTOT / 128, 384, SM_GEMM>>>(
        query, Wq, Wk, Wv, bq, bk, bv, Wo, px);

    // 2) fused flash attention + output projection -> fp32 out
    cudaFuncSetAttribute(attn_fused,
                         cudaFuncAttributeMaxDynamicSharedMemorySize, SM_ATTN);
    attn_fused<<<dim3(SS / 64, BB), 256, SM_ATTN>>>(bo, out);
}

// round 16
// speedup vs baseline: 1.1501x; 1.1501x over previous
#include <cuda_runtime.h>
#include <cuda_fp16.h>
#include <cstdint>

// Problem constants
#define BB 8
#define SS 2048
#define DD 512
#define PP 64
#define MTOT (BB * SS)   // 16384

// ---------------------------------------------------------------------------
// Scratch (__device__ globals)
// ---------------------------------------------------------------------------
__device__ __align__(16) __half g_Wo[512 * 64];      // Wo^T [n=512][k=64] fp16
__device__ __align__(16) __half g_x[(size_t)3 * MTOT * 64];  // q|k|v [region][m][p]

// ---------------------------------------------------------------------------
// Helpers
// ---------------------------------------------------------------------------
__device__ __forceinline__ uint32_t smem_u32(const void* p) {
    uint32_t a;
    asm("{ .reg .u64 t; cvta.to.shared.u64 t, %1; cvt.u32.u64 %0, t; }"
        : "=r"(a) : "l"(p));
    return a;
}
__device__ __forceinline__ uint32_t packh2(float lo, float hi) {
    __half2 h = __floats2half2_rn(lo, hi);
    return *(uint32_t*)&h;
}
__device__ __forceinline__ float ex2(float x) {
    float y;
    asm("ex2.approx.f32 %0, %1;" : "=f"(y) : "f"(x));
    return y;
}
// m16n8k16 fp16 mma, fp32 accumulate
__device__ __forceinline__ void mma16816(float c[4], const uint32_t a[4],
                                         const uint32_t b[2]) {
    asm volatile(
        "mma.sync.aligned.m16n8k16.row.col.f32.f16.f16.f32 "
        "{%0,%1,%2,%3}, {%4,%5,%6,%7}, {%8,%9}, {%0,%1,%2,%3};\n"
        : "+f"(c[0]), "+f"(c[1]), "+f"(c[2]), "+f"(c[3])
        : "r"(a[0]), "r"(a[1]), "r"(a[2]), "r"(a[3]), "r"(b[0]), "r"(b[1]));
}
__device__ __forceinline__ void ldsm4(uint32_t r[4], uint32_t addr) {
    asm volatile("ldmatrix.sync.aligned.m8n8.x4.shared.b16 {%0,%1,%2,%3}, [%4];"
                 : "=r"(r[0]), "=r"(r[1]), "=r"(r[2]), "=r"(r[3]) : "r"(addr));
}
__device__ __forceinline__ void ldsm4t(uint32_t r[4], uint32_t addr) {
    asm volatile("ldmatrix.sync.aligned.m8n8.x4.trans.shared.b16 {%0,%1,%2,%3}, [%4];"
                 : "=r"(r[0]), "=r"(r[1]), "=r"(r[2]), "=r"(r[3]) : "r"(addr));
}
#define CPA(dst, src) \
    asm volatile("cp.async.cg.shared.global [%0], [%1], 16;" \
                 :: "r"(dst), "l"(src) : "memory")
#define CPC() asm volatile("cp.async.commit_group;" ::: "memory")
#define CPW(n) asm volatile("cp.async.wait_group %0;" :: "n"(n) : "memory")

#define STR 72          // fp16 row stride in elements (144 B)
#define ROWB 144
#define QSC (0.125f * 1.4426950408889634f)   // 1/sqrt(P) * log2(e)

// ---------------------------------------------------------------------------
// Merged QKV GEMM: one CTA computes all three regions for a 128-row m-tile.
// 384 threads = 12 warps: wm = w&3 (32-row group), wn = w>>2 (region 0..2).
// A tile converted once (shared by 3x the MMAs); W transposed+converted per
// chunk; register double-buffering. 8 CTAs pack Wo^T fp16 in a prologue.
// ---------------------------------------------------------------------------
__global__ __launch_bounds__(384) void gemm_qkv(
    const float* __restrict__ Af,
    const float* __restrict__ Wq, const float* __restrict__ Wk,
    const float* __restrict__ Wv,
    const float* __restrict__ bq, const float* __restrict__ bk,
    const float* __restrict__ bv,
    const float* __restrict__ Wo, __half* __restrict__ Chg) {
    extern __shared__ char smc[];
    __half* As = (__half*)smc;
    __half* Bs = As + 128 * STR;
    const uint32_t smb = smem_u32(smc);
    const uint32_t Ao = smb, Bo = smb + 128 * ROWB;

    int tid = threadIdx.x, w = tid >> 5, l = tid & 31;
    int wm = w & 3, wn = w >> 2;           // rows wm*32..+32, region wn
    int m0 = blockIdx.x * 128;

    // --- Wo^T pack prologue: 8 CTAs, one 64x64 tile each (register transpose)
    if (blockIdx.x < 8 && tid < 256) {
        int dt = blockIdx.x;
        int rp = tid >> 3, f8 = tid & 7;
        #pragma unroll
        for (int i = 0; i < 2; i++) {
            int f4 = f8 + i * 8;
            float4 a0 = *(const float4*)(Wo + (size_t)(rp * 2)     * 512 + dt * 64 + f4 * 4);
            float4 a1 = *(const float4*)(Wo + (size_t)(rp * 2 + 1) * 512 + dt * 64 + f4 * 4);
            *(uint32_t*)&g_Wo[(size_t)(dt * 64 + f4 * 4 + 0) * 64 + rp * 2] = packh2(a0.x, a1.x);
            *(uint32_t*)&g_Wo[(size_t)(dt * 64 + f4 * 4 + 1) * 64 + rp * 2] = packh2(a0.y, a1.y);
            *(uint32_t*)&g_Wo[(size_t)(dt * 64 + f4 * 4 + 2) * 64 + rp * 2] = packh2(a0.z, a1.z);
            *(uint32_t*)&g_Wo[(size_t)(dt * 64 + f4 * 4 + 3) * 64 + rp * 2] = packh2(a0.w, a1.w);
        }
    }

    // prefetch chunk 0: A (2048 float4, 6 guarded tasks), B (1536 pair tasks, 4)
    float4 aP[6];
    float4 bP0[4], bP1[4];
    #pragma unroll
    for (int i = 0; i < 6; i++) {
        int idx = tid + i * 384;
        if (idx < 2048) {
            int rr = idx >> 4, c4 = idx & 15;
            aP[i] = *(const float4*)(Af + (size_t)(m0 + rr) * DD + c4 * 4);
        }
    }
    #pragma unroll
    for (int i = 0; i < 4; i++) {
        int tix = tid + i * 384;
        int rg2 = tix >> 9, t5 = tix & 511, kp = t5 >> 4, n4 = t5 & 15;
        const float* Wsrc = (rg2 == 0) ? Wq : ((rg2 == 1) ? Wk : Wv);
        const float* base = Wsrc + (size_t)(kp * 2) * 64 + n4 * 4;
        bP0[i] = *(const float4*)base;
        bP1[i] = *(const float4*)(base + 64);
    }

    float c[2][8][4] = {};

    for (int k0 = 0; k0 < DD; k0 += 64) {
        // store prefetched A (fp32->fp16)
        #pragma unroll
        for (int i = 0; i < 6; i++) {
            int idx = tid + i * 384;
            if (idx < 2048) {
                int rr = idx >> 4, c4 = idx & 15;
                float4 v = aP[i];
                *(uint2*)&As[rr * STR + c4 * 4] =
                    make_uint2(packh2(v.x, v.y), packh2(v.z, v.w));
            }
        }
        // store prefetched B (transposed pair-pack, region-scaled)
        #pragma unroll
        for (int i = 0; i < 4; i++) {
            int tix = tid + i * 384;
            int rg2 = tix >> 9, t5 = tix & 511, kp = t5 >> 4, n4 = t5 & 15;
            float s = (rg2 == 0) ? QSC : 1.f;
            float4 v0 = bP0[i], v1 = bP1[i];
            int rn = rg2 * 64 + n4 * 4;
            *(uint32_t*)&Bs[(rn + 0) * STR + kp * 2] = packh2(v0.x * s, v1.x * s);
            *(uint32_t*)&Bs[(rn + 1) * STR + kp * 2] = packh2(v0.y * s, v1.y * s);
            *(uint32_t*)&Bs[(rn + 2) * STR + kp * 2] = packh2(v0.z * s, v1.z * s);
            *(uint32_t*)&Bs[(rn + 3) * STR + kp * 2] = packh2(v0.w * s, v1.w * s);
        }
        __syncthreads();

        // prefetch next chunk (overlaps MMAs below)
        if (k0 + 64 < DD) {
            int kn = k0 + 64;
            #pragma unroll
            for (int i = 0; i < 6; i++) {
                int idx = tid + i * 384;
                if (idx < 2048) {
                    int rr = idx >> 4, c4 = idx & 15;
                    aP[i] = *(const float4*)(Af + (size_t)(m0 + rr) * DD + kn + c4 * 4);
                }
            }
            #pragma unroll
            for (int i = 0; i < 4; i++) {
                int tix = tid + i * 384;
                int rg2 = tix >> 9, t5 = tix & 511, kp = t5 >> 4, n4 = t5 & 15;
                const float* Wsrc = (rg2 == 0) ? Wq : ((rg2 == 1) ? Wk : Wv);
                const float* base = Wsrc + (size_t)(kn + kp * 2) * 64 + n4 * 4;
                bP0[i] = *(const float4*)base;
                bP1[i] = *(const float4*)(base + 64);
            }
        }

        // warp GEMM: c[32 x 64 of region wn] += A-chunk @ B-chunk^T
        {
            int r = l & 15, cc = l >> 4;
            #pragma unroll
            for (int j = 0; j < 4; j++) {
                uint32_t a0[4], a1[4];
                uint32_t aoff = (wm * 32 + r) * ROWB + (j * 2 + cc) * 16;
                ldsm4(a0, Ao + aoff);
                ldsm4(a1, Ao + aoff + 16 * ROWB);
                #pragma unroll
                for (int np = 0; np < 4; np++) {
                    uint32_t bb[4];
                    ldsm4(bb, Bo + (wn * 64 + np * 16 + r) * ROWB + (j * 2 + cc) * 16);
                    uint32_t be[2] = { bb[0], bb[2] }, bo_[2] = { bb[1], bb[3] };
                    mma16816(c[0][np * 2],     a0, be);
                    mma16816(c[1][np * 2],     a1, be);
                    mma16816(c[0][np * 2 + 1], a0, bo_);
                    mma16816(c[1][np * 2 + 1], a1, bo_);
                }
            }
        }
        __syncthreads();
    }

    // epilogue: bias + fp16 store to region wn
    size_t reg = (size_t)wn * MTOT * 64;
    const float* bsrc = (wn == 0) ? bq : ((wn == 1) ? bk : bv);
    const float bscale = (wn == 0) ? QSC : 1.f;
    #pragma unroll
    for (int mt = 0; mt < 2; mt++)
        #pragma unroll
        for (int nt = 0; nt < 8; nt++) {
            int row = m0 + wm * 32 + mt * 16 + (l >> 2);
            int col = nt * 8 + (l & 3) * 2;
            float b0 = bsrc[col] * bscale, b1 = bsrc[col + 1] * bscale;
            *(uint32_t*)&Chg[reg + (size_t)row * 64 + col] =
                packh2(c[mt][nt][0] + b0, c[mt][nt][1] + b1);
            *(uint32_t*)&Chg[reg + (size_t)(row + 8) * 64 + col] =
                packh2(c[mt][nt][2] + b0, c[mt][nt][3] + b1);
        }
}

// ---------------------------------------------------------------------------
// Fused flash attention + output projection, 4-stage KV ring with ONE
// barrier per tile. CTA = 256 threads / 64 q-rows; warp w: rg=w&3 (16 rows),
// kh=w>>2 (32 of 64 keys). FA2 cross-tile pipeline (softmax(t) || S(t+1)).
// Ring hazard: load for t+2 targets the slot of tile t-2, whose readers all
// finished before the body(t-1) barrier. No-max softmax (bounded scores).
// Mask term: per-row pre-softmax constant -> shift-invariant no-op.
// (Round-14 version — best measured; R15 interleave regressed via reg spill.)
// ---------------------------------------------------------------------------
#define TILEB (64 * ROWB)      // 9216 B per 64x64 fp16 tile
#define STAGEB (2 * TILEB)     // k, v (also one 128-row Wo pass)
#define NT (SS / 64)           // 32; NT&3 == 0
#define TSTEP (64 * 128)       // global bytes per KV tile
// smem: [slot0..3 | O-tile fp16 | lpart];  p32 partials reuse slot 2
#define OT_OFF  (4 * STAGEB)
#define LP_OFF  (4 * STAGEB + TILEB)
#define SM_ATTN (4 * STAGEB + TILEB + 8 * 16 * 4)
#define P32STR 66              // fp32 partial-O row stride (floats)

__device__ __forceinline__ void load_stage(uint32_t stb, const char* k,
                                           const char* v, int tid) {
    #pragma unroll
    for (int i = 0; i < 2; i++) {
        int idx = tid + i * 256;
        int row = idx >> 3, c = idx & 7;
        uint32_t d = stb + row * ROWB + c * 16;
        size_t g = (size_t)row * 128 + c * 16;
        CPA(d,         k + g);
        CPA(d + TILEB, v + g);
    }
}
__device__ __forceinline__ void load_wo(uint32_t stb, int pass, int tid) {
    const char* wop = (const char*)g_Wo;
    #pragma unroll
    for (int i = 0; i < 4; i++) {
        int idx = tid + i * 256;
        int row = idx >> 3, c = idx & 7;
        CPA(stb + row * ROWB + c * 16,
            wop + ((size_t)(pass * 128 + row) * 64 + c * 8) * 2);
    }
}

__device__ __forceinline__ void spass_h(float s[4][4], const uint32_t qf[4][4],
                                        uint32_t Kb, int kh, int r, int cc) {
    #pragma unroll
    for (int j = 0; j < 4; j++) {
        #pragma unroll
        for (int np = 0; np < 2; np++) {
            uint32_t bb[4];
            ldsm4(bb, Kb + ((kh * 2 + np) * 16 + r) * ROWB + (j * 2 + cc) * 16);
            uint32_t be[2] = { bb[0], bb[2] }, bo_[2] = { bb[1], bb[3] };
            mma16816(s[np * 2],     qf[j], be);
            mma16816(s[np * 2 + 1], qf[j], bo_);
        }
    }
}
__device__ __forceinline__ void pv_h(float o[8][4], const uint32_t pf[2][4],
                                     uint32_t Vb, int kh, int r, int cc) {
    #pragma unroll
    for (int j = 0; j < 2; j++) {
        #pragma unroll
        for (int np = 0; np < 4; np++) {
            uint32_t bb[4];
            ldsm4t(bb, Vb + (kh * 32 + j * 16 + r) * ROWB + np * 32 + cc * 16);
            uint32_t be[2] = { bb[0], bb[1] }, bo_[2] = { bb[2], bb[3] };
            mma16816(o[np * 2],     pf[j], be);
            mma16816(o[np * 2 + 1], pf[j], bo_);
        }
    }
}

// body(t): issue load(t+2) [or Wo pass 0/1 at the tail]; ONE barrier;
// softmax(scur); snxt = S(t+1); O += P_t V(t).
__device__ __forceinline__ void attn_body(
    int t, float (&scur)[4][4], float (&snxt)[4][4],
    float (&o)[8][4], float& l0r, float& l1r,
    const uint32_t (&qf)[4][4],
    uint32_t st0, const char* k0p, const char* v0p,
    int kh, int r, int cc, int tid) {
    if (t + 2 < NT) {
        size_t g = (size_t)(t + 2) * TSTEP;
        load_stage(st0 + ((t + 2) & 3) * STAGEB, k0p + g, v0p + g, tid);
        CPC();
        CPW(1);                 // tile t+1 resident (t+2 may fly)
    } else if (t + 2 == NT) {
        load_wo(st0 + 0 * STAGEB, 0, tid);   // Wo pass 0 -> slot 0 (tile NT-4's slot)
        CPC();
        CPW(1);                 // tile NT-1 resident (Wo0 may fly)
    } else {                    // t == NT-1
        load_wo(st0 + 1 * STAGEB, 1, tid);   // Wo pass 1 -> slot 1
        CPC();                  // nothing to wait on
    }
    __syncthreads();

    // softmax on scur (tile t): p = 2^s
    #pragma unroll
    for (int nt = 0; nt < 4; nt++) {
        scur[nt][0] = ex2(scur[nt][0]);
        scur[nt][1] = ex2(scur[nt][1]);
        scur[nt][2] = ex2(scur[nt][2]);
        scur[nt][3] = ex2(scur[nt][3]);
        l0r += scur[nt][0] + scur[nt][1];
        l1r += scur[nt][2] + scur[nt][3];
    }
    uint32_t pf[2][4];
    #pragma unroll
    for (int j = 0; j < 2; j++) {
        const float* s0 = scur[2 * j];
        const float* s1 = scur[2 * j + 1];
        pf[j][0] = packh2(s0[0], s0[1]);
        pf[j][1] = packh2(s0[2], s0[3]);
        pf[j][2] = packh2(s1[0], s1[1]);
        pf[j][3] = packh2(s1[2], s1[3]);
    }

    // S(t+1) — independent; overlaps softmax result latency and PV below
    #pragma unroll
    for (int a = 0; a < 4; a++)
        #pragma unroll
        for (int bq2 = 0; bq2 < 4; bq2++) snxt[a][bq2] = 0.f;
    if (t + 1 < NT)
        spass_h(snxt, qf, st0 + ((t + 1) & 3) * STAGEB, kh, r, cc);

    // PV(t)
    pv_h(o, pf, st0 + (t & 3) * STAGEB + TILEB, kh, r, cc);
    // no trailing barrier: next body's load targets the t-1 slot, whose
    // readers all finished before THIS body's barrier.
}

__global__ __launch_bounds__(256) void attn_fused(const float* __restrict__ bo_g,
                                                  float* __restrict__ out) {
    extern __shared__ char smc[];
    const uint32_t st0 = smem_u32(smc);

    int tid = threadIdx.x, w = tid >> 5, l = tid & 31;
    int rg = w & 3, kh = w >> 2;
    int b = blockIdx.y, m0 = blockIdx.x * 64;
    size_t rb = (size_t)b * SS + m0;
    int rbase = rg * 16;
    int r = l & 15, cc = l >> 4;

    const __half* q = g_x + rb * 64;
    const char* k0p = (const char*)(g_x + ((size_t)MTOT + (size_t)b * SS) * 64);
    const char* v0p = (const char*)(g_x + ((size_t)2 * MTOT + (size_t)b * SS) * 64);

    // prologue: slots 0 and 1 in flight
    load_stage(st0,          k0p,         v0p,         tid); CPC();
    load_stage(st0 + STAGEB, k0p + TSTEP, v0p + TSTEP, tid); CPC();

    // Q fragments straight from global (m16n8k16 A-frag layout)
    uint32_t qf[4][4];
    {
        int fr = rbase + (l >> 2);
        int fc = (l & 3) * 2;
        #pragma unroll
        for (int j = 0; j < 4; j++) {
            size_t base0 = (size_t)fr * 64 + j * 16 + fc;
            size_t base1 = base0 + 8 * 64;
            qf[j][0] = *(const uint32_t*)(q + base0);
            qf[j][1] = *(const uint32_t*)(q + base1);
            qf[j][2] = *(const uint32_t*)(q + base0 + 8);
            qf[j][3] = *(const uint32_t*)(q + base1 + 8);
        }
    }

    CPW(1);            // slot 0 resident
    __syncthreads();

    float sA[4][4] = {}, sB[4][4] = {};
    spass_h(sA, qf, st0, kh, r, cc);      // S(0)

    float o[8][4] = {};
    float l0r = 0.f, l1r = 0.f;

    for (int t = 0; t < NT; t += 2) {
        attn_body(t,     sA, sB, o, l0r, l1r, qf, st0, k0p, v0p, kh, r, cc, tid);
        attn_body(t + 1, sB, sA, o, l0r, l1r, qf, st0, k0p, v0p, kh, r, cc, tid);
    }

    // quad-reduce partial l
    l0r += __shfl_xor_sync(~0u, l0r, 1);
    l0r += __shfl_xor_sync(~0u, l0r, 2);
    l1r += __shfl_xor_sync(~0u, l1r, 1);
    l1r += __shfl_xor_sync(~0u, l1r, 2);

    // publish partials: l for all warps; fp32 O for kh=1 -> slot 2
    // (slot 2 held tile NT-2; its readers finished before body(NT-1) barrier)
    float* lp = (float*)(smc + LP_OFF);
    if ((l & 3) == 0) {
        lp[w * 16 + (l >> 2)]     = l0r;
        lp[w * 16 + 8 + (l >> 2)] = l1r;
    }
    float* p32 = (float*)(smc + 2 * STAGEB);
    if (kh == 1) {
        #pragma unroll
        for (int nt = 0; nt < 8; nt++) {
            int col = nt * 8 + (l & 3) * 2;
            int row = rbase + (l >> 2);
            *(float2*)&p32[row * P32STR + col]       = make_float2(o[nt][0], o[nt][1]);
            *(float2*)&p32[(row + 8) * P32STR + col] = make_float2(o[nt][2], o[nt][3]);
        }
    }
    __syncthreads();

    // kh=0 warps: combine partials, normalize, publish fp16 O tile
    if (kh == 0) {
        float l0c = l0r + lp[(w + 4) * 16 + (l >> 2)];
        float l1c = l1r + lp[(w + 4) * 16 + 8 + (l >> 2)];
        float i0 = 1.f / l0c, i1 = 1.f / l1c;
        __half* ot = (__half*)(smc + OT_OFF);
        #pragma unroll
        for (int nt = 0; nt < 8; nt++) {
            int col = nt * 8 + (l & 3) * 2;
            int row = rbase + (l >> 2);
            float2 a = *(const float2*)&p32[row * P32STR + col];
            float2 bq2 = *(const float2*)&p32[(row + 8) * P32STR + col];
            *(uint32_t*)&ot[row * STR + col] =
                packh2((o[nt][0] + a.x) * i0, (o[nt][1] + a.y) * i0);
            *(uint32_t*)&ot[(row + 8) * STR + col] =
                packh2((o[nt][2] + bq2.x) * i1, (o[nt][3] + bq2.y) * i1);
        }
    }
    __syncthreads();

    // all warps: load O a-frags (K=64) from the fp16 tile
    uint32_t of[4][4];
    {
        uint32_t OTb = st0 + OT_OFF;
        #pragma unroll
        for (int j = 0; j < 4; j++)
            ldsm4(of[j], OTb + (rbase + r) * ROWB + (j * 2 + cc) * 16);
    }

    // Wo projection: passes 0..3 in slots 0,1,3,0; Wo0/Wo1 already in flight.
    // Warp halves split the 8 column-groups (kh*4 + np).
    size_t r0g = rb + rbase + (l >> 2), r1g = r0g + 8;

    load_wo(st0 + 3 * STAGEB, 2, tid);   // Wo2 -> slot 3 (tile NT-1's slot, now free)
    CPC();

    const int pass_slot[4] = { 0, 1, 3, 0 };
    #pragma unroll
    for (int pass = 0; pass < 4; pass++) {
        // wait for this pass's Wo rows: groups younger than it may still fly
        if (pass == 0)      { CPW(2); }   // flight: Wo1, Wo2
        else if (pass == 1) { CPW(2); }   // flight: Wo2, Wo3
        else if (pass == 2) { CPW(1); }   // flight: Wo3
        else                { CPW(0); }
        __syncthreads();
        uint32_t Wb = st0 + pass_slot[pass] * STAGEB;
        #pragma unroll
        for (int np = 0; np < 4; np++) {
            int npg = kh * 4 + np;
            float ce[4] = {}, co[4] = {};
            #pragma unroll
            for (int j = 0; j < 4; j++) {
                uint32_t bb[4];
                ldsm4(bb, Wb + (npg * 16 + r) * ROWB + (j * 2 + cc) * 16);
                uint32_t be[2] = { bb[0], bb[2] }, bo_[2] = { bb[1], bb[3] };
                mma16816(ce, of[j], be);
                mma16816(co, of[j], bo_);
            }
            int c0 = pass * 128 + npg * 16 + (l & 3) * 2;
            int c1 = c0 + 8;
            float be0 = bo_g[c0], be1 = bo_g[c0 + 1];
            float bO0 = bo_g[c1], bO1 = bo_g[c1 + 1];
            *(float2*)&out[r0g * DD + c0] = make_float2(ce[0] + be0, ce[1] + be1);
            *(float2*)&out[r1g * DD + c0] = make_float2(ce[2] + be0, ce[3] + be1);
            *(float2*)&out[r0g * DD + c1] = make_float2(co[0] + bO0, co[1] + bO1);
            *(float2*)&out[r1g * DD + c1] = make_float2(co[2] + bO0, co[3] + bO1);
        }
        if (pass == 0) {
            __syncthreads();                     // all warps done reading slot 0
            load_wo(st0 + 0 * STAGEB, 3, tid);   // Wo3 -> slot 0
            CPC();
        }
    }
}

// ---------------------------------------------------------------------------
// kernel_launch
// Inputs: query, attention_mask, Wq, bq, Wk, bk, Wv, bv, Wo, bo
// ---------------------------------------------------------------------------
extern "C" void kernel_launch(void* const* d_in, const int* in_sizes, int n_in,
                              void* d_out, int out_size) {
    const float* query = (const float*)d_in[0];
    const float* Wq = (const float*)d_in[2];
    const float* bq = (const float*)d_in[3];
    const float* Wk = (const float*)d_in[4];
    const float* bk = (const float*)d_in[5];
    const float* Wv = (const float*)d_in[6];
    const float* bv = (const float*)d_in[7];
    const float* Wo = (const float*)d_in[8];
    const float* bo = (const float*)d_in[9];
    float* out = (float*)d_out;

    __half* px;
    cudaGetSymbolAddress((void**)&px, g_x);

    constexpr int SM_GEMM = (128 + 192) * ROWB;   // 46080 B

    // 1) merged QKV projection (one A convert shared by all 3 regions)
    cudaFuncSetAttribute(gemm_qkv,
                         cudaFuncAttributeMaxDynamicSharedMemorySize, SM_GEMM);
    gemm_qkv<<<MTOT / 128, 384, SM_GEMM>>>(
        query, Wq, Wk, Wv, bq, bk, bv, Wo, px);

    // 2) fused flash attention + output projection -> fp32 out
    cudaFuncSetAttribute(attn_fused,
                         cudaFuncAttributeMaxDynamicSharedMemorySize, SM_ATTN);
    attn_fused<<<dim3(SS / 64, BB), 256, SM_ATTN>>>(bo, out);
}

// round 17
// speedup vs baseline: 1.2284x; 1.0680x over previous
#include <cuda_runtime.h>
#include <cuda_fp16.h>
#include <cstdint>

// Problem constants
#define BB 8
#define SS 2048
#define DD 512
#define PP 64
#define MTOT (BB * SS)   // 16384

// ---------------------------------------------------------------------------
// Scratch (__device__ globals)
// ---------------------------------------------------------------------------
__device__ __align__(16) __half g_Wo[512 * 64];      // Wo^T [n=512][k=64] fp16
__device__ __align__(16) __half g_x[(size_t)3 * MTOT * 64];  // q|k|v [region][m][p]

// ---------------------------------------------------------------------------
// Helpers
// ---------------------------------------------------------------------------
__device__ __forceinline__ uint32_t smem_u32(const void* p) {
    uint32_t a;
    asm("{ .reg .u64 t; cvta.to.shared.u64 t, %1; cvt.u32.u64 %0, t; }"
        : "=r"(a) : "l"(p));
    return a;
}
__device__ __forceinline__ uint32_t packh2(float lo, float hi) {
    __half2 h = __floats2half2_rn(lo, hi);
    return *(uint32_t*)&h;
}
__device__ __forceinline__ float ex2(float x) {
    float y;
    asm("ex2.approx.f32 %0, %1;" : "=f"(y) : "f"(x));
    return y;
}
// m16n8k16 fp16 mma, fp32 accumulate
__device__ __forceinline__ void mma16816(float c[4], const uint32_t a[4],
                                         const uint32_t b[2]) {
    asm volatile(
        "mma.sync.aligned.m16n8k16.row.col.f32.f16.f16.f32 "
        "{%0,%1,%2,%3}, {%4,%5,%6,%7}, {%8,%9}, {%0,%1,%2,%3};\n"
        : "+f"(c[0]), "+f"(c[1]), "+f"(c[2]), "+f"(c[3])
        : "r"(a[0]), "r"(a[1]), "r"(a[2]), "r"(a[3]), "r"(b[0]), "r"(b[1]));
}
__device__ __forceinline__ void ldsm4(uint32_t r[4], uint32_t addr) {
    asm volatile("ldmatrix.sync.aligned.m8n8.x4.shared.b16 {%0,%1,%2,%3}, [%4];"
                 : "=r"(r[0]), "=r"(r[1]), "=r"(r[2]), "=r"(r[3]) : "r"(addr));
}
__device__ __forceinline__ void ldsm4t(uint32_t r[4], uint32_t addr) {
    asm volatile("ldmatrix.sync.aligned.m8n8.x4.trans.shared.b16 {%0,%1,%2,%3}, [%4];"
                 : "=r"(r[0]), "=r"(r[1]), "=r"(r[2]), "=r"(r[3]) : "r"(addr));
}
#define CPA(dst, src) \
    asm volatile("cp.async.cg.shared.global [%0], [%1], 16;" \
                 :: "r"(dst), "l"(src) : "memory")
#define CPC() asm volatile("cp.async.commit_group;" ::: "memory")
#define CPW(n) asm volatile("cp.async.wait_group %0;" :: "n"(n) : "memory")

#define STR 72          // fp16 row stride in elements (144 B)
#define ROWB 144
#define QSC (0.125f * 1.4426950408889634f)   // 1/sqrt(P) * log2(e)

// ---------------------------------------------------------------------------
// Merged QKV GEMM: one CTA computes all three regions for a 128-row m-tile.
// 384 threads = 12 warps: wm = w&3 (32-row group), wn = w>>2 (region 0..2).
// A tile converted once (shared by 3x the MMAs). B chunk kept K-MAJOR in
// smem (W's natural layout -> no transposing stores; 8 STS.64 + 16 packs
// per thread per chunk instead of 32 STS.32 + 32 packs) and consumed with
// ldmatrix.trans (same verified pattern as V in the attention kernel).
// Register double-buffering on both operand chunk loads.
// 8 CTAs pack Wo^T fp16 in a prologue for the attention epilogue.
// ---------------------------------------------------------------------------
#define BSTR 200        // B smem row stride in elements (400 B; 400%128=16)
#define BROWB 400

__global__ __launch_bounds__(384) void gemm_qkv(
    const float* __restrict__ Af,
    const float* __restrict__ Wq, const float* __restrict__ Wk,
    const float* __restrict__ Wv,
    const float* __restrict__ bq, const float* __restrict__ bk,
    const float* __restrict__ bv,
    const float* __restrict__ Wo, __half* __restrict__ Chg) {
    extern __shared__ char smc[];
    __half* As = (__half*)smc;
    __half* Bs = As + 128 * STR;          // B: 64 k-rows x 192 n (k-major)
    const uint32_t smb = smem_u32(smc);
    const uint32_t Ao = smb, Bo = smb + 128 * ROWB;

    int tid = threadIdx.x, w = tid >> 5, l = tid & 31;
    int wm = w & 3, wn = w >> 2;           // rows wm*32..+32, region wn
    int m0 = blockIdx.x * 128;

    // --- Wo^T pack prologue: 8 CTAs, one 64x64 tile each (register transpose)
    if (blockIdx.x < 8 && tid < 256) {
        int dt = blockIdx.x;
        int rp = tid >> 3, f8 = tid & 7;
        #pragma unroll
        for (int i = 0; i < 2; i++) {
            int f4 = f8 + i * 8;
            float4 a0 = *(const float4*)(Wo + (size_t)(rp * 2)     * 512 + dt * 64 + f4 * 4);
            float4 a1 = *(const float4*)(Wo + (size_t)(rp * 2 + 1) * 512 + dt * 64 + f4 * 4);
            *(uint32_t*)&g_Wo[(size_t)(dt * 64 + f4 * 4 + 0) * 64 + rp * 2] = packh2(a0.x, a1.x);
            *(uint32_t*)&g_Wo[(size_t)(dt * 64 + f4 * 4 + 1) * 64 + rp * 2] = packh2(a0.y, a1.y);
            *(uint32_t*)&g_Wo[(size_t)(dt * 64 + f4 * 4 + 2) * 64 + rp * 2] = packh2(a0.z, a1.z);
            *(uint32_t*)&g_Wo[(size_t)(dt * 64 + f4 * 4 + 3) * 64 + rp * 2] = packh2(a0.w, a1.w);
        }
    }

    // prefetch chunk 0.
    // A: 2048 float4 tasks (6 guarded rounds). B: 3072 float4 tasks (8 rounds);
    // task -> region = idx>>10, row k = (idx&1023)>>4, n4 = idx&15.
    float4 aP[6];
    float4 bP[8];
    #pragma unroll
    for (int i = 0; i < 6; i++) {
        int idx = tid + i * 384;
        if (idx < 2048) {
            int rr = idx >> 4, c4 = idx & 15;
            aP[i] = *(const float4*)(Af + (size_t)(m0 + rr) * DD + c4 * 4);
        }
    }
    #pragma unroll
    for (int i = 0; i < 8; i++) {
        int idx = tid + i * 384;
        int rg2 = idx >> 10, rem = idx & 1023, kr = rem >> 4, n4 = rem & 15;
        const float* Wsrc = (rg2 == 0) ? Wq : ((rg2 == 1) ? Wk : Wv);
        bP[i] = *(const float4*)(Wsrc + (size_t)kr * 64 + n4 * 4);
    }

    float c[2][8][4] = {};

    for (int k0 = 0; k0 < DD; k0 += 64) {
        // store prefetched A (fp32->fp16)
        #pragma unroll
        for (int i = 0; i < 6; i++) {
            int idx = tid + i * 384;
            if (idx < 2048) {
                int rr = idx >> 4, c4 = idx & 15;
                float4 v = aP[i];
                *(uint2*)&As[rr * STR + c4 * 4] =
                    make_uint2(packh2(v.x, v.y), packh2(v.z, v.w));
            }
        }
        // store prefetched B (k-major, no transpose; region 0 scaled)
        #pragma unroll
        for (int i = 0; i < 8; i++) {
            int idx = tid + i * 384;
            int rg2 = idx >> 10, rem = idx & 1023, kr = rem >> 4, n4 = rem & 15;
            float s = (rg2 == 0) ? QSC : 1.f;
            float4 v = bP[i];
            *(uint2*)&Bs[kr * BSTR + rg2 * 64 + n4 * 4] =
                make_uint2(packh2(v.x * s, v.y * s), packh2(v.z * s, v.w * s));
        }
        __syncthreads();

        // prefetch next chunk (overlaps MMAs below)
        if (k0 + 64 < DD) {
            int kn = k0 + 64;
            #pragma unroll
            for (int i = 0; i < 6; i++) {
                int idx = tid + i * 384;
                if (idx < 2048) {
                    int rr = idx >> 4, c4 = idx & 15;
                    aP[i] = *(const float4*)(Af + (size_t)(m0 + rr) * DD + kn + c4 * 4);
                }
            }
            #pragma unroll
            for (int i = 0; i < 8; i++) {
                int idx = tid + i * 384;
                int rg2 = idx >> 10, rem = idx & 1023, kr = rem >> 4, n4 = rem & 15;
                const float* Wsrc = (rg2 == 0) ? Wq : ((rg2 == 1) ? Wk : Wv);
                bP[i] = *(const float4*)(Wsrc + (size_t)(kn + kr) * 64 + n4 * 4);
            }
        }

        // warp GEMM: c[32 x 64 of region wn] += A-chunk @ B-chunk
        // (B-frags via ldmatrix.trans on the k-major tile — V pattern)
        {
            int r = l & 15, cc = l >> 4;
            #pragma unroll
            for (int j = 0; j < 4; j++) {
                uint32_t a0[4], a1[4];
                uint32_t aoff = (wm * 32 + r) * ROWB + (j * 2 + cc) * 16;
                ldsm4(a0, Ao + aoff);
                ldsm4(a1, Ao + aoff + 16 * ROWB);
                #pragma unroll
                for (int np = 0; np < 4; np++) {
                    uint32_t bb[4];
                    ldsm4t(bb, Bo + (j * 16 + r) * BROWB + wn * 128 + np * 32 + cc * 16);
                    uint32_t be[2] = { bb[0], bb[1] }, bo_[2] = { bb[2], bb[3] };
                    mma16816(c[0][np * 2],     a0, be);
                    mma16816(c[1][np * 2],     a1, be);
                    mma16816(c[0][np * 2 + 1], a0, bo_);
                    mma16816(c[1][np * 2 + 1], a1, bo_);
                }
            }
        }
        __syncthreads();
    }

    // epilogue: bias + fp16 store to region wn
    size_t reg = (size_t)wn * MTOT * 64;
    const float* bsrc = (wn == 0) ? bq : ((wn == 1) ? bk : bv);
    const float bscale = (wn == 0) ? QSC : 1.f;
    #pragma unroll
    for (int mt = 0; mt < 2; mt++)
        #pragma unroll
        for (int nt = 0; nt < 8; nt++) {
            int row = m0 + wm * 32 + mt * 16 + (l >> 2);
            int col = nt * 8 + (l & 3) * 2;
            float b0 = bsrc[col] * bscale, b1 = bsrc[col + 1] * bscale;
            *(uint32_t*)&Chg[reg + (size_t)row * 64 + col] =
                packh2(c[mt][nt][0] + b0, c[mt][nt][1] + b1);
            *(uint32_t*)&Chg[reg + (size_t)(row + 8) * 64 + col] =
                packh2(c[mt][nt][2] + b0, c[mt][nt][3] + b1);
        }
}

// ---------------------------------------------------------------------------
// Fused flash attention + output projection, 4-stage KV ring with ONE
// barrier per tile (round-14 version — best measured, protected).
// ---------------------------------------------------------------------------
#define TILEB (64 * ROWB)      // 9216 B per 64x64 fp16 tile
#define STAGEB (2 * TILEB)     // k, v (also one 128-row Wo pass)
#define NT (SS / 64)           // 32; NT&3 == 0
#define TSTEP (64 * 128)       // global bytes per KV tile
// smem: [slot0..3 | O-tile fp16 | lpart];  p32 partials reuse slot 2
#define OT_OFF  (4 * STAGEB)
#define LP_OFF  (4 * STAGEB + TILEB)
#define SM_ATTN (4 * STAGEB + TILEB + 8 * 16 * 4)
#define P32STR 66              // fp32 partial-O row stride (floats)

__device__ __forceinline__ void load_stage(uint32_t stb, const char* k,
                                           const char* v, int tid) {
    #pragma unroll
    for (int i = 0; i < 2; i++) {
        int idx = tid + i * 256;
        int row = idx >> 3, c = idx & 7;
        uint32_t d = stb + row * ROWB + c * 16;
        size_t g = (size_t)row * 128 + c * 16;
        CPA(d,         k + g);
        CPA(d + TILEB, v + g);
    }
}
__device__ __forceinline__ void load_wo(uint32_t stb, int pass, int tid) {
    const char* wop = (const char*)g_Wo;
    #pragma unroll
    for (int i = 0; i < 4; i++) {
        int idx = tid + i * 256;
        int row = idx >> 3, c = idx & 7;
        CPA(stb + row * ROWB + c * 16,
            wop + ((size_t)(pass * 128 + row) * 64 + c * 8) * 2);
    }
}

__device__ __forceinline__ void spass_h(float s[4][4], const uint32_t qf[4][4],
                                        uint32_t Kb, int kh, int r, int cc) {
    #pragma unroll
    for (int j = 0; j < 4; j++) {
        #pragma unroll
        for (int np = 0; np < 2; np++) {
            uint32_t bb[4];
            ldsm4(bb, Kb + ((kh * 2 + np) * 16 + r) * ROWB + (j * 2 + cc) * 16);
            uint32_t be[2] = { bb[0], bb[2] }, bo_[2] = { bb[1], bb[3] };
            mma16816(s[np * 2],     qf[j], be);
            mma16816(s[np * 2 + 1], qf[j], bo_);
        }
    }
}
__device__ __forceinline__ void pv_h(float o[8][4], const uint32_t pf[2][4],
                                     uint32_t Vb, int kh, int r, int cc) {
    #pragma unroll
    for (int j = 0; j < 2; j++) {
        #pragma unroll
        for (int np = 0; np < 4; np++) {
            uint32_t bb[4];
            ldsm4t(bb, Vb + (kh * 32 + j * 16 + r) * ROWB + np * 32 + cc * 16);
            uint32_t be[2] = { bb[0], bb[1] }, bo_[2] = { bb[2], bb[3] };
            mma16816(o[np * 2],     pf[j], be);
            mma16816(o[np * 2 + 1], pf[j], bo_);
        }
    }
}

// body(t): issue load(t+2) [or Wo pass 0/1 at the tail]; ONE barrier;
// softmax(scur); snxt = S(t+1); O += P_t V(t).
__device__ __forceinline__ void attn_body(
    int t, float (&scur)[4][4], float (&snxt)[4][4],
    float (&o)[8][4], float& l0r, float& l1r,
    const uint32_t (&qf)[4][4],
    uint32_t st0, const char* k0p, const char* v0p,
    int kh, int r, int cc, int tid) {
    if (t + 2 < NT) {
        size_t g = (size_t)(t + 2) * TSTEP;
        load_stage(st0 + ((t + 2) & 3) * STAGEB, k0p + g, v0p + g, tid);
        CPC();
        CPW(1);                 // tile t+1 resident (t+2 may fly)
    } else if (t + 2 == NT) {
        load_wo(st0 + 0 * STAGEB, 0, tid);   // Wo pass 0 -> slot 0
        CPC();
        CPW(1);                 // tile NT-1 resident (Wo0 may fly)
    } else {                    // t == NT-1
        load_wo(st0 + 1 * STAGEB, 1, tid);   // Wo pass 1 -> slot 1
        CPC();                  // nothing to wait on
    }
    __syncthreads();

    // softmax on scur (tile t): p = 2^s
    #pragma unroll
    for (int nt = 0; nt < 4; nt++) {
        scur[nt][0] = ex2(scur[nt][0]);
        scur[nt][1] = ex2(scur[nt][1]);
        scur[nt][2] = ex2(scur[nt][2]);
        scur[nt][3] = ex2(scur[nt][3]);
        l0r += scur[nt][0] + scur[nt][1];
        l1r += scur[nt][2] + scur[nt][3];
    }
    uint32_t pf[2][4];
    #pragma unroll
    for (int j = 0; j < 2; j++) {
        const float* s0 = scur[2 * j];
        const float* s1 = scur[2 * j + 1];
        pf[j][0] = packh2(s0[0], s0[1]);
        pf[j][1] = packh2(s0[2], s0[3]);
        pf[j][2] = packh2(s1[0], s1[1]);
        pf[j][3] = packh2(s1[2], s1[3]);
    }

    // S(t+1) — independent; overlaps softmax result latency and PV below
    #pragma unroll
    for (int a = 0; a < 4; a++)
        #pragma unroll
        for (int bq2 = 0; bq2 < 4; bq2++) snxt[a][bq2] = 0.f;
    if (t + 1 < NT)
        spass_h(snxt, qf, st0 + ((t + 1) & 3) * STAGEB, kh, r, cc);

    // PV(t)
    pv_h(o, pf, st0 + (t & 3) * STAGEB + TILEB, kh, r, cc);
    // no trailing barrier: next body's load targets the t-1 slot, whose
    // readers all finished before THIS body's barrier.
}

__global__ __launch_bounds__(256) void attn_fused(const float* __restrict__ bo_g,
                                                  float* __restrict__ out) {
    extern __shared__ char smc[];
    const uint32_t st0 = smem_u32(smc);

    int tid = threadIdx.x, w = tid >> 5, l = tid & 31;
    int rg = w & 3, kh = w >> 2;
    int b = blockIdx.y, m0 = blockIdx.x * 64;
    size_t rb = (size_t)b * SS + m0;
    int rbase = rg * 16;
    int r = l & 15, cc = l >> 4;

    const __half* q = g_x + rb * 64;
    const char* k0p = (const char*)(g_x + ((size_t)MTOT + (size_t)b * SS) * 64);
    const char* v0p = (const char*)(g_x + ((size_t)2 * MTOT + (size_t)b * SS) * 64);

    // prologue: slots 0 and 1 in flight
    load_stage(st0,          k0p,         v0p,         tid); CPC();
    load_stage(st0 + STAGEB, k0p + TSTEP, v0p + TSTEP, tid); CPC();

    // Q fragments straight from global (m16n8k16 A-frag layout)
    uint32_t qf[4][4];
    {
        int fr = rbase + (l >> 2);
        int fc = (l & 3) * 2;
        #pragma unroll
        for (int j = 0; j < 4; j++) {
            size_t base0 = (size_t)fr * 64 + j * 16 + fc;
            size_t base1 = base0 + 8 * 64;
            qf[j][0] = *(const uint32_t*)(q + base0);
            qf[j][1] = *(const uint32_t*)(q + base1);
            qf[j][2] = *(const uint32_t*)(q + base0 + 8);
            qf[j][3] = *(const uint32_t*)(q + base1 + 8);
        }
    }

    CPW(1);            // slot 0 resident
    __syncthreads();

    float sA[4][4] = {}, sB[4][4] = {};
    spass_h(sA, qf, st0, kh, r, cc);      // S(0)

    float o[8][4] = {};
    float l0r = 0.f, l1r = 0.f;

    for (int t = 0; t < NT; t += 2) {
        attn_body(t,     sA, sB, o, l0r, l1r, qf, st0, k0p, v0p, kh, r, cc, tid);
        attn_body(t + 1, sB, sA, o, l0r, l1r, qf, st0, k0p, v0p, kh, r, cc, tid);
    }

    // quad-reduce partial l
    l0r += __shfl_xor_sync(~0u, l0r, 1);
    l0r += __shfl_xor_sync(~0u, l0r, 2);
    l1r += __shfl_xor_sync(~0u, l1r, 1);
    l1r += __shfl_xor_sync(~0u, l1r, 2);

    // publish partials: l for all warps; fp32 O for kh=1 -> slot 2
    float* lp = (float*)(smc + LP_OFF);
    if ((l & 3) == 0) {
        lp[w * 16 + (l >> 2)]     = l0r;
        lp[w * 16 + 8 + (l >> 2)] = l1r;
    }
    float* p32 = (float*)(smc + 2 * STAGEB);
    if (kh == 1) {
        #pragma unroll
        for (int nt = 0; nt < 8; nt++) {
            int col = nt * 8 + (l & 3) * 2;
            int row = rbase + (l >> 2);
            *(float2*)&p32[row * P32STR + col]       = make_float2(o[nt][0], o[nt][1]);
            *(float2*)&p32[(row + 8) * P32STR + col] = make_float2(o[nt][2], o[nt][3]);
        }
    }
    __syncthreads();

    // kh=0 warps: combine partials, normalize, publish fp16 O tile
    if (kh == 0) {
        float l0c = l0r + lp[(w + 4) * 16 + (l >> 2)];
        float l1c = l1r + lp[(w + 4) * 16 + 8 + (l >> 2)];
        float i0 = 1.f / l0c, i1 = 1.f / l1c;
        __half* ot = (__half*)(smc + OT_OFF);
        #pragma unroll
        for (int nt = 0; nt < 8; nt++) {
            int col = nt * 8 + (l & 3) * 2;
            int row = rbase + (l >> 2);
            float2 a = *(const float2*)&p32[row * P32STR + col];
            float2 bq2 = *(const float2*)&p32[(row + 8) * P32STR + col];
            *(uint32_t*)&ot[row * STR + col] =
                packh2((o[nt][0] + a.x) * i0, (o[nt][1] + a.y) * i0);
            *(uint32_t*)&ot[(row + 8) * STR + col] =
                packh2((o[nt][2] + bq2.x) * i1, (o[nt][3] + bq2.y) * i1);
        }
    }
    __syncthreads();

    // all warps: load O a-frags (K=64) from the fp16 tile
    uint32_t of[4][4];
    {
        uint32_t OTb = st0 + OT_OFF;
        #pragma unroll
        for (int j = 0; j < 4; j++)
            ldsm4(of[j], OTb + (rbase + r) * ROWB + (j * 2 + cc) * 16);
    }

    // Wo projection: passes 0..3 in slots 0,1,3,0; Wo0/Wo1 already in flight.
    size_t r0g = rb + rbase + (l >> 2), r1g = r0g + 8;

    load_wo(st0 + 3 * STAGEB, 2, tid);   // Wo2 -> slot 3 (tile NT-1's slot, now free)
    CPC();

    const int pass_slot[4] = { 0, 1, 3, 0 };
    #pragma unroll
    for (int pass = 0; pass < 4; pass++) {
        if (pass == 0)      { CPW(2); }   // flight: Wo1, Wo2
        else if (pass == 1) { CPW(2); }   // flight: Wo2, Wo3
        else if (pass == 2) { CPW(1); }   // flight: Wo3
        else                { CPW(0); }
        __syncthreads();
        uint32_t Wb = st0 + pass_slot[pass] * STAGEB;
        #pragma unroll
        for (int np = 0; np < 4; np++) {
            int npg = kh * 4 + np;
            float ce[4] = {}, co[4] = {};
            #pragma unroll
            for (int j = 0; j < 4; j++) {
                uint32_t bb[4];
                ldsm4(bb, Wb + (npg * 16 + r) * ROWB + (j * 2 + cc) * 16);
                uint32_t be[2] = { bb[0], bb[2] }, bo_[2] = { bb[1], bb[3] };
                mma16816(ce, of[j], be);
                mma16816(co, of[j], bo_);
            }
            int c0 = pass * 128 + npg * 16 + (l & 3) * 2;
            int c1 = c0 + 8;
            float be0 = bo_g[c0], be1 = bo_g[c0 + 1];
            float bO0 = bo_g[c1], bO1 = bo_g[c1 + 1];
            *(float2*)&out[r0g * DD + c0] = make_float2(ce[0] + be0, ce[1] + be1);
            *(float2*)&out[r1g * DD + c0] = make_float2(ce[2] + be0, ce[3] + be1);
            *(float2*)&out[r0g * DD + c1] = make_float2(co[0] + bO0, co[1] + bO1);
            *(float2*)&out[r1g * DD + c1] = make_float2(co[2] + bO0, co[3] + bO1);
        }
        if (pass == 0) {
            __syncthreads();                     // all warps done reading slot 0
            load_wo(st0 + 0 * STAGEB, 3, tid);   // Wo3 -> slot 0
            CPC();
        }
    }
}

// ---------------------------------------------------------------------------
// kernel_launch
// Inputs: query, attention_mask, Wq, bq, Wk, bk, Wv, bv, Wo, bo
// ---------------------------------------------------------------------------
extern "C" void kernel_launch(void* const* d_in, const int* in_sizes, int n_in,
                              void* d_out, int out_size) {
    const float* query = (const float*)d_in[0];
    const float* Wq = (const float*)d_in[2];
    const float* bq = (const float*)d_in[3];
    const float* Wk = (const float*)d_in[4];
    const float* bk = (const float*)d_in[5];
    const float* Wv = (const float*)d_in[6];
    const float* bv = (const float*)d_in[7];
    const float* Wo = (const float*)d_in[8];
    const float* bo = (const float*)d_in[9];
    float* out = (float*)d_out;

    __half* px;
    cudaGetSymbolAddress((void**)&px, g_x);

    constexpr int SM_GEMM = 128 * ROWB + 64 * BROWB;   // 18432 + 25600 = 44032

    // 1) merged QKV projection (k-major B via ldmatrix.trans)
    cudaFuncSetAttribute(gemm_qkv,
                         cudaFuncAttributeMaxDynamicSharedMemorySize, SM_GEMM);
    gemm_qkv<<<MTOT / 128, 384, SM_GEMM>>>(
        query, Wq, Wk, Wv, bq, bk, bv, Wo, px);

    // 2) fused flash attention + output projection -> fp32 out
    cudaFuncSetAttribute(attn_fused,
                         cudaFuncAttributeMaxDynamicSharedMemorySize, SM_ATTN);
    attn_fused<<<dim3(SS / 64, BB), 256, SM_ATTN>>>(bo, out);
}